// round 4
// baseline (speedup 1.0000x reference)
#include <cuda_runtime.h>

// Problem constants
#define BATCH   256
#define INDIM   159     // L1*(DIM+1) + L2
#define MDIM    93      // L2*DIM
#define MATEL   2976
#define KPATHS  64
#define NCLS    10
#define SIGDIM  340     // 4+16+64+256
#define KD      159

// ---------------- scratch (no allocations allowed) ----------------
__device__ __align__(16) float g_mean[BATCH * MDIM];
__device__ __align__(16) float g_cov [BATCH * MATEL];
__device__ __align__(16) float g_newV[BATCH * MDIM * KPATHS];     // [b][r][k]
__device__ __align__(16) float g_part[BATCH * 4 * SIGDIM];        // per (b, kgroup) partial sig sums

// =====================================================================
// Kernel 1: out[b,n] = x[b,:] . W[n,:] + bias[n]    (M=256, K=159)
// Tiles: 32 (batch) x 64 (n); W chunked over K in 3x53 to fit static smem.
// =====================================================================
__global__ __launch_bounds__(256) void gemm_kernel(
    const float* __restrict__ X, const float* __restrict__ W,
    const float* __restrict__ bias, float* __restrict__ out, int N)
{
    __shared__ float Ash[32 * KD];      // 20.3 KB
    __shared__ float Wsh[53 * 65];      // 13.8 KB (padded stride 65)

    int tid = threadIdx.x;
    int n0  = blockIdx.x * 64;
    int b0  = blockIdx.y * 32;

    for (int idx = tid; idx < 32 * KD; idx += 256)
        Ash[idx] = X[(b0 + idx / KD) * KD + (idx % KD)];

    float acc[4][2] = {};
    int tn = tid & 31;          // n pair index (2 cols each)
    int tb = tid >> 5;          // 0..7 -> 4 batch rows each

    for (int kc = 0; kc < 3; kc++) {
        __syncthreads();
        for (int idx = tid; idx < 64 * 53; idx += 256) {
            int n = idx / 53, c = idx % 53;
            float v = (n0 + n < N) ? W[(n0 + n) * KD + kc * 53 + c] : 0.f;
            Wsh[c * 65 + n] = v;
        }
        __syncthreads();
        #pragma unroll 4
        for (int c = 0; c < 53; c++) {
            int k = kc * 53 + c;
            float w0 = Wsh[c * 65 + tn * 2];
            float w1 = Wsh[c * 65 + tn * 2 + 1];
            #pragma unroll
            for (int j = 0; j < 4; j++) {
                float a = Ash[(tb * 4 + j) * KD + k];
                acc[j][0] = fmaf(a, w0, acc[j][0]);
                acc[j][1] = fmaf(a, w1, acc[j][1]);
            }
        }
    }
    #pragma unroll
    for (int j = 0; j < 4; j++)
        #pragma unroll
        for (int i = 0; i < 2; i++) {
            int n = n0 + tn * 2 + i;
            if (n < N)
                out[(b0 + tb * 4 + j) * N + n] = acc[j][i] + bias[n];
        }
}

// =====================================================================
// Kernel 2: per-batch scatter sqrtCov -> M (93x93, banded lower-tri),
// then newV[b,r,k] = mean[b,r] + sum_c M[r,c]*eps[b,c,k].
// Band: M[r,c] nonzero only when c < (r/3+1)*3.
// =====================================================================
__global__ __launch_bounds__(256) void newv_kernel(
    const float* __restrict__ eps, const int* __restrict__ xI,
    const int* __restrict__ yI)
{
    __shared__ float Msh[MDIM * MDIM];     // 34.6 KB
    int b   = blockIdx.x;
    int tid = threadIdx.x;

    for (int i = tid; i < MDIM * MDIM; i += 256) Msh[i] = 0.f;
    __syncthreads();
    for (int e = tid; e < MATEL; e += 256)
        Msh[xI[e] * MDIM + yI[e]] = g_cov[b * MATEL + e];
    __syncthreads();

    int k4 = tid & 15;     // k = k4*4 .. +3 (float4)
    int rg = tid >> 4;     // rows rg, rg+16, ...
    const float* epsB = eps + (size_t)b * MDIM * KPATHS + k4 * 4;

    for (int r = rg; r < MDIM; r += 16) {
        float a0 = 0.f, a1 = 0.f, a2 = 0.f, a3 = 0.f;
        int cmax = (r / 3 + 1) * 3;
        for (int c = 0; c < cmax; c++) {
            float4 ev = *(const float4*)(epsB + c * KPATHS);
            float  mv = Msh[r * MDIM + c];
            a0 = fmaf(mv, ev.x, a0);
            a1 = fmaf(mv, ev.y, a1);
            a2 = fmaf(mv, ev.z, a2);
            a3 = fmaf(mv, ev.w, a3);
        }
        float mn = g_mean[b * MDIM + r];
        float4 res = make_float4(a0 + mn, a1 + mn, a2 + mn, a3 + mn);
        *(float4*)(&g_newV[(size_t)b * MDIM * KPATHS + r * KPATHS + k4 * 4]) = res;
    }
}

// =====================================================================
// Kernel 3: signature (level 4, D=4) + tensor normalization + partial
// K-mean. 16 lanes per path: lane owns prefix (i1,i2); keeps
// S2 (1), S3[i3] (4), S4[i3][i4] (16) in registers; S1 replicated.
// Chen step in Horner form (all updates read old lower levels).
// Block = 256 threads = 16 paths; grid = B*4 (kgroups of 16 of K=64).
// =====================================================================
#define SIG_STEP(c0_, c1_, c2_, c3_) do {                                         \
    float dx0 = (c0_) - p0, dx1 = (c1_) - p1, dx2 = (c2_) - p2, dx3 = (c3_) - p3; \
    p0 = (c0_); p1 = (c1_); p2 = (c2_); p3 = (c3_);                               \
    float du = (i1 == 0) ? dx0 : ((i1 == 1) ? dx1 : ((i1 == 2) ? dx2 : dx3));     \
    float dv = (i2 == 0) ? dx0 : ((i2 == 1) ? dx1 : ((i2 == 2) ? dx2 : dx3));     \
    float cc1 = fmaf(0.25f, du, s1u);                                             \
    float cc2 = fmaf((1.0f/3.0f) * dv, cc1, s2);                                  \
    float hh;                                                                     \
    hh = fmaf(0.5f*dx0, cc2, s3[0]);                                              \
    s4[0] = fmaf(dx0,hh,s4[0]);  s4[1] = fmaf(dx1,hh,s4[1]);                      \
    s4[2] = fmaf(dx2,hh,s4[2]);  s4[3] = fmaf(dx3,hh,s4[3]);                      \
    hh = fmaf(0.5f*dx1, cc2, s3[1]);                                              \
    s4[4] = fmaf(dx0,hh,s4[4]);  s4[5] = fmaf(dx1,hh,s4[5]);                      \
    s4[6] = fmaf(dx2,hh,s4[6]);  s4[7] = fmaf(dx3,hh,s4[7]);                      \
    hh = fmaf(0.5f*dx2, cc2, s3[2]);                                              \
    s4[8] = fmaf(dx0,hh,s4[8]);  s4[9] = fmaf(dx1,hh,s4[9]);                      \
    s4[10]= fmaf(dx2,hh,s4[10]); s4[11]= fmaf(dx3,hh,s4[11]);                     \
    hh = fmaf(0.5f*dx3, cc2, s3[3]);                                              \
    s4[12]= fmaf(dx0,hh,s4[12]); s4[13]= fmaf(dx1,hh,s4[13]);                     \
    s4[14]= fmaf(dx2,hh,s4[14]); s4[15]= fmaf(dx3,hh,s4[15]);                     \
    float c1b = fmaf((1.0f/3.0f), du, s1u);                                       \
    float m3v = fmaf(0.5f*dv, c1b, s2);                                           \
    s3[0] = fmaf(dx0, m3v, s3[0]); s3[1] = fmaf(dx1, m3v, s3[1]);                 \
    s3[2] = fmaf(dx2, m3v, s3[2]); s3[3] = fmaf(dx3, m3v, s3[3]);                 \
    s2 = fmaf(dv, fmaf(0.5f, du, s1u), s2);                                       \
    s1x += dx0; s1y += dx1; s1z += dx2; s1t += dx3; s1u += du;                    \
} while (0)

__global__ __launch_bounds__(256) void sig_kernel(const float* __restrict__ x)
{
    __shared__ float xsh[INDIM];          // known points + times
    __shared__ float nsh[MDIM * 16];      // newV for this kgroup: [row93][16]
    __shared__ float sacc[SIGDIM];

    int b   = blockIdx.x >> 2;
    int kg  = blockIdx.x & 3;
    int tid = threadIdx.x;

    for (int i = tid; i < INDIM; i += 256) xsh[i] = x[b * INDIM + i];
    for (int i = tid; i < MDIM * 16; i += 256) {
        int r = i >> 4, kp = i & 15;
        nsh[i] = g_newV[(size_t)b * MDIM * KPATHS + r * KPATHS + kg * 16 + kp];
    }
    for (int i = tid; i < SIGDIM; i += 256) sacc[i] = 0.f;
    __syncthreads();

    int p   = tid >> 4;    // path within block (0..15) -> k = kg*16+p
    int pre = tid & 15;    // (i1,i2) prefix
    int i1  = pre >> 2, i2 = pre & 3;

    // path point 0 = known point 0
    float p0 = xsh[0], p1 = xsh[1], p2 = xsh[2], p3 = xsh[96];
    float s1x = 0.f, s1y = 0.f, s1z = 0.f, s1t = 0.f, s1u = 0.f, s2 = 0.f;
    float s3[4] = {0.f, 0.f, 0.f, 0.f};
    float s4[16] = {0.f,0.f,0.f,0.f,0.f,0.f,0.f,0.f,0.f,0.f,0.f,0.f,0.f,0.f,0.f,0.f};

    for (int m = 0; m < 31; m++) {
        {   // odd path index: new (midpoint) point m
            int base = (m * 3) * 16 + p;
            float c0 = nsh[base], c1v = nsh[base + 16], c2v = nsh[base + 32];
            float c3v = xsh[128 + m];            // t of point id 32+m
            SIG_STEP(c0, c1v, c2v, c3v);
        }
        {   // even path index: known point m+1
            int kb = (m + 1) * 3;
            float c0 = xsh[kb], c1v = xsh[kb + 1], c2v = xsh[kb + 2];
            float c3v = xsh[97 + m];             // t of point id m+1
            SIG_STEP(c0, c1v, c2v, c3v);
        }
    }

    // ---- norms (reduce over the 16 lanes of this path) ----
    float n1 = s1x*s1x + s1y*s1y + s1z*s1z + s1t*s1t;   // replicated
    float n2 = s2 * s2;
    float n3 = s3[0]*s3[0] + s3[1]*s3[1] + s3[2]*s3[2] + s3[3]*s3[3];
    float n4 = 0.f;
    #pragma unroll
    for (int j = 0; j < 16; j++) n4 = fmaf(s4[j], s4[j], n4);
    #pragma unroll
    for (int off = 8; off >= 1; off >>= 1) {
        n2 += __shfl_xor_sync(0xffffffffu, n2, off);
        n3 += __shfl_xor_sync(0xffffffffu, n3, off);
        n4 += __shfl_xor_sync(0xffffffffu, n4, off);
    }

    float norm2 = 1.0f + (((n1 + n2) + n3) + n4);
    float xc  = fmaxf(norm2, 4.0f);
    float psi = (norm2 <= 4.0f) ? norm2 : (4.0f + 16.0f * (0.25f - 1.0f / xc));

    float lo = 0.f, hi = 1.f;
    #pragma unroll 4
    for (int it = 0; it < 40; it++) {
        float mid = 0.5f * (lo + hi);
        float m2 = mid * mid, m4 = m2 * m2;
        float m6 = m4 * m2,   m8 = m4 * m4;
        float val = 1.0f + (((m2 * n1 + m4 * n2) + m6 * n3) + m8 * n4);
        bool pos = val > psi;
        hi = pos ? mid : hi;
        lo = pos ? lo : mid;
    }
    float lam  = 0.5f * (lo + hi);
    float lam2 = lam * lam, lam3 = lam2 * lam, lam4 = lam2 * lam2;

    // ---- accumulate normalized sig of this path into block accumulator ----
    if (pre == 0) {
        atomicAdd(&sacc[0], lam * s1x);
        atomicAdd(&sacc[1], lam * s1y);
        atomicAdd(&sacc[2], lam * s1z);
        atomicAdd(&sacc[3], lam * s1t);
    }
    atomicAdd(&sacc[4 + pre], lam2 * s2);
    #pragma unroll
    for (int j = 0; j < 4; j++)
        atomicAdd(&sacc[20 + pre * 4 + j], lam3 * s3[j]);
    #pragma unroll
    for (int j = 0; j < 16; j++)
        atomicAdd(&sacc[84 + pre * 16 + j], lam4 * s4[j]);
    __syncthreads();

    for (int i = tid; i < SIGDIM; i += 256)
        g_part[(b * 4 + kg) * SIGDIM + i] = sacc[i];
}

// =====================================================================
// Kernel 4: sig mean over K, final linear (10x340), log_softmax.
// One warp per batch row.
// =====================================================================
__global__ void final_kernel(const float* __restrict__ Wf,
                             const float* __restrict__ bf,
                             float* __restrict__ out)
{
    int b = blockIdx.x;
    int lane = threadIdx.x;
    __shared__ float sh[SIGDIM];
    const float* gp = &g_part[b * 4 * SIGDIM];
    for (int j = lane; j < SIGDIM; j += 32)
        sh[j] = (gp[j] + gp[SIGDIM + j] + gp[2 * SIGDIM + j] + gp[3 * SIGDIM + j])
                * (1.0f / (float)KPATHS);
    __syncwarp();

    float logit = -3.402823466e38f;
    if (lane < NCLS) {
        float acc = bf[lane];
        const float* wr = Wf + lane * SIGDIM;
        for (int j = 0; j < SIGDIM; j++) acc = fmaf(sh[j], wr[j], acc);
        logit = acc;
    }
    float mx = logit;
    #pragma unroll
    for (int off = 16; off; off >>= 1)
        mx = fmaxf(mx, __shfl_xor_sync(0xffffffffu, mx, off));
    float e = (lane < NCLS) ? expf(logit - mx) : 0.f;
    float ssum = e;
    #pragma unroll
    for (int off = 16; off; off >>= 1)
        ssum += __shfl_xor_sync(0xffffffffu, ssum, off);
    if (lane < NCLS)
        out[b * NCLS + lane] = logit - mx - logf(ssum);
}

// =====================================================================
extern "C" void kernel_launch(void* const* d_in, const int* in_sizes, int n_in,
                              void* d_out, int out_size)
{
    const float* x      = (const float*)d_in[0];
    const float* W_mean = (const float*)d_in[1];
    const float* b_mean = (const float*)d_in[2];
    const float* W_cov  = (const float*)d_in[3];
    const float* b_cov  = (const float*)d_in[4];
    const float* W_fin  = (const float*)d_in[5];
    const float* b_fin  = (const float*)d_in[6];
    const float* eps    = (const float*)d_in[7];
    const int*   x_idx  = (const int*)  d_in[8];
    const int*   y_idx  = (const int*)  d_in[9];
    float* out = (float*)d_out;

    float* gmean; cudaGetSymbolAddress((void**)&gmean, g_mean);
    float* gcov;  cudaGetSymbolAddress((void**)&gcov,  g_cov);

    // 1) mean = x @ W_mean^T + b_mean   [256,93]
    gemm_kernel<<<dim3((MDIM + 63) / 64, BATCH / 32), 256>>>(x, W_mean, b_mean, gmean, MDIM);
    // 2) sqrtCov = x @ W_cov^T + b_cov  [256,2976]
    gemm_kernel<<<dim3((MATEL + 63) / 64, BATCH / 32), 256>>>(x, W_cov, b_cov, gcov, MATEL);
    // 3) scatter + banded batched matmul -> newV [256,93,64]
    newv_kernel<<<BATCH, 256>>>(eps, x_idx, y_idx);
    // 4) signatures + normalization + partial K-sums
    sig_kernel<<<BATCH * 4, 256>>>(x);
    // 5) K-mean + final linear + log_softmax
    final_kernel<<<BATCH, 32>>>(W_fin, b_fin, out);
}

// round 5
// speedup vs baseline: 1.1485x; 1.1485x over previous
#include <cuda_runtime.h>

// Problem constants
#define BATCH   256
#define INDIM   159     // L1*(DIM+1) + L2
#define MDIM    93      // L2*DIM
#define MATEL   2976
#define KPATHS  64
#define NCLS    10
#define SIGDIM  340     // 4+16+64+256
#define KD      159
#define KC      40      // gemm k-chunk

// ---------------- scratch (no allocations allowed) ----------------
__device__ __align__(16) float g_mean[BATCH * MDIM];
__device__ __align__(16) float g_cov [BATCH * MATEL];
__device__ __align__(16) float g_newV[BATCH * MDIM * KPATHS];     // [b][r][k]
__device__ __align__(16) float g_part[BATCH * 4 * SIGDIM];        // per (b,kgroup) partial sums

// =====================================================================
// Kernel 1 (fused): mean = x@W_mean^T + b_mean  AND  cov = x@W_cov^T + b_cov
// Block tile: 32 batch x 128 n; 4x4 register tile per thread.
// blockIdx.x 0..23 -> cov columns; blockIdx.x == 24 -> mean (N=93).
// =====================================================================
__global__ __launch_bounds__(256) void gemm_kernel(
    const float* __restrict__ X,
    const float* __restrict__ Wc, const float* __restrict__ bc,
    const float* __restrict__ Wm, const float* __restrict__ bm)
{
    __shared__ float Ash[32][160];     // 20.0 KB (col 159 zero pad)
    __shared__ float Wsh[KC][132];     // 20.6 KB (pad for store conflicts, 16B-aligned rows)

    bool is_mean = (blockIdx.x == 24);
    const float* W    = is_mean ? Wm : Wc;
    const float* bias = is_mean ? bm : bc;
    float*       out  = is_mean ? g_mean : g_cov;
    int N  = is_mean ? MDIM : MATEL;
    int n0 = is_mean ? 0 : blockIdx.x * 128;
    int b0 = blockIdx.y * 32;
    int tid = threadIdx.x;

    for (int idx = tid; idx < 32 * 160; idx += 256) {
        int r = idx / 160, k = idx % 160;
        Ash[r][k] = (k < KD) ? X[(b0 + r) * KD + k] : 0.f;
    }

    float acc[4][4] = {};
    int tn = tid & 31;          // 4 consecutive n
    int tb = tid >> 5;          // 4 consecutive batch rows

    for (int k0 = 0; k0 < KD; k0 += KC) {
        __syncthreads();
        for (int idx = tid; idx < KC * 128; idx += 256) {
            int n = idx / KC, k = idx % KC;
            int gk = k0 + k, gn = n0 + n;
            Wsh[k][n] = (gk < KD && gn < N) ? W[(size_t)gn * KD + gk] : 0.f;
        }
        __syncthreads();
        #pragma unroll 8
        for (int k = 0; k < KC; k++) {
            float4 w = *(const float4*)&Wsh[k][tn * 4];
            #pragma unroll
            for (int j = 0; j < 4; j++) {
                float a = Ash[tb * 4 + j][k0 + k];
                acc[j][0] = fmaf(a, w.x, acc[j][0]);
                acc[j][1] = fmaf(a, w.y, acc[j][1]);
                acc[j][2] = fmaf(a, w.z, acc[j][2]);
                acc[j][3] = fmaf(a, w.w, acc[j][3]);
            }
        }
    }
    #pragma unroll
    for (int j = 0; j < 4; j++)
        #pragma unroll
        for (int i = 0; i < 4; i++) {
            int n = n0 + tn * 4 + i;
            if (n < N)
                out[(size_t)(b0 + tb * 4 + j) * N + n] = acc[j][i] + bias[n];
        }
}

// =====================================================================
// Kernel 2: scatter sqrtCov -> banded M (93x93), newV = M@eps + mean.
// 3-row register blocking (rows of a group share the band limit) and
// balanced pairing: thread-group tg handles bands tg and 30-tg
// (combined width constant = 96 cols), killing intra-block imbalance.
// =====================================================================
__global__ __launch_bounds__(256) void newv_kernel(
    const float* __restrict__ eps, const int* __restrict__ xI,
    const int* __restrict__ yI)
{
    __shared__ float Msh[MDIM * MDIM];     // 34.6 KB
    int b   = blockIdx.x;
    int tid = threadIdx.x;

    for (int i = tid; i < MDIM * MDIM; i += 256) Msh[i] = 0.f;
    __syncthreads();
    const float* covB = g_cov + (size_t)b * MATEL;
    for (int e = tid; e < MATEL; e += 256)
        Msh[xI[e] * MDIM + yI[e]] = covB[e];
    __syncthreads();

    int k4 = tid & 15;     // float4 of k: k = k4*4..+3
    int tg = tid >> 4;     // band-group index 0..15
    const float* epsB = eps    + (size_t)b * MDIM * KPATHS + k4 * 4;
    float*       outB = g_newV + (size_t)b * MDIM * KPATHS + k4 * 4;

    #pragma unroll
    for (int pass = 0; pass < 2; pass++) {
        if (pass == 1 && tg == 15) break;          // g=15 handled in pass 0
        int g    = pass ? 30 - tg : tg;
        int r0   = 3 * g;
        int cmax = 3 * g + 3;
        float a0x=0,a0y=0,a0z=0,a0w=0, a1x=0,a1y=0,a1z=0,a1w=0, a2x=0,a2y=0,a2z=0,a2w=0;
        const float* M0 = &Msh[r0 * MDIM];
        for (int c = 0; c < cmax; c++) {
            float4 ev = *(const float4*)(epsB + (size_t)c * KPATHS);
            float m0 = M0[c], m1 = M0[MDIM + c], m2 = M0[2 * MDIM + c];
            a0x = fmaf(m0, ev.x, a0x); a0y = fmaf(m0, ev.y, a0y);
            a0z = fmaf(m0, ev.z, a0z); a0w = fmaf(m0, ev.w, a0w);
            a1x = fmaf(m1, ev.x, a1x); a1y = fmaf(m1, ev.y, a1y);
            a1z = fmaf(m1, ev.z, a1z); a1w = fmaf(m1, ev.w, a1w);
            a2x = fmaf(m2, ev.x, a2x); a2y = fmaf(m2, ev.y, a2y);
            a2z = fmaf(m2, ev.z, a2z); a2w = fmaf(m2, ev.w, a2w);
        }
        float mn0 = g_mean[b * MDIM + r0];
        float mn1 = g_mean[b * MDIM + r0 + 1];
        float mn2 = g_mean[b * MDIM + r0 + 2];
        *(float4*)(outB + (size_t)(r0    ) * KPATHS) = make_float4(a0x+mn0, a0y+mn0, a0z+mn0, a0w+mn0);
        *(float4*)(outB + (size_t)(r0 + 1) * KPATHS) = make_float4(a1x+mn1, a1y+mn1, a1z+mn1, a1w+mn1);
        *(float4*)(outB + (size_t)(r0 + 2) * KPATHS) = make_float4(a2x+mn2, a2y+mn2, a2z+mn2, a2w+mn2);
    }
}

// =====================================================================
// Kernel 3: signature (level 4, D=4) + normalization + partial K-mean.
// 16 lanes per path (prefix i1,i2); S2/S3/S4 register-resident.
// Points packed as float4 (coords+time) -> 1 broadcast LDS.128/step.
// S1 x/y/z/t telescope (endpoint - start) => removed from the loop.
// Block = 512 thr = 32 paths (2 kgroups); 100% occupancy at 2 blocks/SM.
// =====================================================================
#define SIG_STEP(c0_, c1_, c2_, c3_) do {                                         \
    float dx0 = (c0_) - p0, dx1 = (c1_) - p1, dx2 = (c2_) - p2, dx3 = (c3_) - p3; \
    p0 = (c0_); p1 = (c1_); p2 = (c2_); p3 = (c3_);                               \
    float du = (i1 == 0) ? dx0 : ((i1 == 1) ? dx1 : ((i1 == 2) ? dx2 : dx3));     \
    float dv = (i2 == 0) ? dx0 : ((i2 == 1) ? dx1 : ((i2 == 2) ? dx2 : dx3));     \
    float cc1 = fmaf(0.25f, du, s1u);                                             \
    float cc2 = fmaf((1.0f/3.0f) * dv, cc1, s2);                                  \
    float hh;                                                                     \
    hh = fmaf(0.5f*dx0, cc2, s3[0]);                                              \
    s4[0] = fmaf(dx0,hh,s4[0]);  s4[1] = fmaf(dx1,hh,s4[1]);                      \
    s4[2] = fmaf(dx2,hh,s4[2]);  s4[3] = fmaf(dx3,hh,s4[3]);                      \
    hh = fmaf(0.5f*dx1, cc2, s3[1]);                                              \
    s4[4] = fmaf(dx0,hh,s4[4]);  s4[5] = fmaf(dx1,hh,s4[5]);                      \
    s4[6] = fmaf(dx2,hh,s4[6]);  s4[7] = fmaf(dx3,hh,s4[7]);                      \
    hh = fmaf(0.5f*dx2, cc2, s3[2]);                                              \
    s4[8] = fmaf(dx0,hh,s4[8]);  s4[9] = fmaf(dx1,hh,s4[9]);                      \
    s4[10]= fmaf(dx2,hh,s4[10]); s4[11]= fmaf(dx3,hh,s4[11]);                     \
    hh = fmaf(0.5f*dx3, cc2, s3[3]);                                              \
    s4[12]= fmaf(dx0,hh,s4[12]); s4[13]= fmaf(dx1,hh,s4[13]);                     \
    s4[14]= fmaf(dx2,hh,s4[14]); s4[15]= fmaf(dx3,hh,s4[15]);                     \
    float c1b = fmaf((1.0f/3.0f), du, s1u);                                       \
    float m3v = fmaf(0.5f*dv, c1b, s2);                                           \
    s3[0] = fmaf(dx0, m3v, s3[0]); s3[1] = fmaf(dx1, m3v, s3[1]);                 \
    s3[2] = fmaf(dx2, m3v, s3[2]); s3[3] = fmaf(dx3, m3v, s3[3]);                 \
    s2 = fmaf(dv, fmaf(0.5f, du, s1u), s2);                                       \
    s1u += du;                                                                    \
} while (0)

__global__ __launch_bounds__(512, 2) void sig_kernel(const float* __restrict__ x)
{
    __shared__ float4 ksh4[32];             // known points (coords, t)
    __shared__ float4 nsh4[2][31][16];      // new points [kgl][m][p] (coords, t)
    __shared__ float  sacc[2][SIGDIM];

    int b    = blockIdx.x >> 1;
    int half = blockIdx.x & 1;
    int tid  = threadIdx.x;
    const float* xb = x + (size_t)b * INDIM;

    if (tid < 32)
        ksh4[tid] = make_float4(xb[3*tid], xb[3*tid+1], xb[3*tid+2], xb[96 + tid]);

    // pack new points: coords from g_newV (coalesced over p), time from x
    const float* nvb = g_newV + (size_t)b * MDIM * KPATHS + half * 32;
    for (int i = tid; i < 2 * 31 * 3 * 16; i += 512) {
        int p = i & 15;
        int t1 = i >> 4;
        int j  = t1 % 3;
        int t2 = t1 / 3;
        int m  = t2 % 31;
        int kgl = t2 / 31;
        ((float*)&nsh4[kgl][m][p])[j] = nvb[(size_t)(3*m + j) * KPATHS + kgl * 16 + p];
    }
    for (int i = tid; i < 2 * 31 * 16; i += 512) {
        int p = i & 15;
        int t = i >> 4;
        int m = t % 31;
        int kgl = t / 31;
        ((float*)&nsh4[kgl][m][p])[3] = xb[128 + m];
    }
    for (int i = tid; i < 2 * SIGDIM; i += 512) sacc[0][i] = 0.f;
    __syncthreads();

    int path = tid >> 4;        // 0..31
    int kgl  = path >> 4;       // kgroup within block
    int p16  = path & 15;
    int pre  = tid & 15;
    int i1 = pre >> 2, i2 = pre & 3;
    const float4* nrow = &nsh4[kgl][0][p16];

    float4 P0 = ksh4[0];
    float p0 = P0.x, p1 = P0.y, p2 = P0.z, p3 = P0.w;
    float s1u = 0.f, s2 = 0.f;
    float s3[4] = {0.f, 0.f, 0.f, 0.f};
    float s4[16] = {0.f,0.f,0.f,0.f,0.f,0.f,0.f,0.f,0.f,0.f,0.f,0.f,0.f,0.f,0.f,0.f};

    float4 cn = nrow[0];
    float4 ck = ksh4[1];
    for (int m = 0; m < 31; m++) {
        int mn = (m < 30) ? m + 1 : 30;
        float4 cnN = nrow[mn * 16];      // prefetch next iteration
        float4 ckN = ksh4[mn + 1];
        SIG_STEP(cn.x, cn.y, cn.z, cn.w);    // midpoint m (id 32+m)
        SIG_STEP(ck.x, ck.y, ck.z, ck.w);    // known point m+1
        cn = cnN; ck = ckN;
    }

    // S1 by telescoping
    float s1x = p0 - P0.x, s1y = p1 - P0.y, s1z = p2 - P0.z, s1t = p3 - P0.w;

    // ---- norms (reduce over 16 prefix lanes) ----
    float n1 = s1x*s1x + s1y*s1y + s1z*s1z + s1t*s1t;   // replicated
    float n2 = s2 * s2;
    float n3 = s3[0]*s3[0] + s3[1]*s3[1] + s3[2]*s3[2] + s3[3]*s3[3];
    float n4 = 0.f;
    #pragma unroll
    for (int j = 0; j < 16; j++) n4 = fmaf(s4[j], s4[j], n4);
    #pragma unroll
    for (int off = 8; off >= 1; off >>= 1) {
        n2 += __shfl_xor_sync(0xffffffffu, n2, off);
        n3 += __shfl_xor_sync(0xffffffffu, n3, off);
        n4 += __shfl_xor_sync(0xffffffffu, n4, off);
    }

    float norm2 = 1.0f + (((n1 + n2) + n3) + n4);
    float xc  = fmaxf(norm2, 4.0f);
    float psi = (norm2 <= 4.0f) ? norm2 : (4.0f + 16.0f * (0.25f - 1.0f / xc));

    float lo = 0.f, hi = 1.f;
    #pragma unroll 4
    for (int it = 0; it < 40; it++) {
        float mid = 0.5f * (lo + hi);
        float m2 = mid * mid, m4 = m2 * m2;
        float m6 = m4 * m2,   m8 = m4 * m4;
        float val = 1.0f + (((m2 * n1 + m4 * n2) + m6 * n3) + m8 * n4);
        bool pos = val > psi;
        hi = pos ? mid : hi;
        lo = pos ? lo : mid;
    }
    float lam  = 0.5f * (lo + hi);
    float lam2 = lam * lam, lam3 = lam2 * lam, lam4 = lam2 * lam2;

    float* sa = sacc[kgl];
    if (pre == 0) {
        atomicAdd(&sa[0], lam * s1x);
        atomicAdd(&sa[1], lam * s1y);
        atomicAdd(&sa[2], lam * s1z);
        atomicAdd(&sa[3], lam * s1t);
    }
    atomicAdd(&sa[4 + pre], lam2 * s2);
    #pragma unroll
    for (int j = 0; j < 4; j++)
        atomicAdd(&sa[20 + pre * 4 + j], lam3 * s3[j]);
    #pragma unroll
    for (int j = 0; j < 16; j++)
        atomicAdd(&sa[84 + pre * 16 + j], lam4 * s4[j]);
    __syncthreads();

    for (int i = tid; i < 2 * SIGDIM; i += 512) {
        int kg2 = i / SIGDIM, r = i % SIGDIM;
        g_part[(size_t)(b * 4 + half * 2 + kg2) * SIGDIM + r] = sacc[kg2][r];
    }
}

// =====================================================================
// Kernel 4: K-mean, final linear (10x340), log_softmax. Warp per batch.
// =====================================================================
__global__ __launch_bounds__(256) void final_kernel(
    const float* __restrict__ Wf, const float* __restrict__ bf,
    float* __restrict__ out)
{
    __shared__ float sh[8][SIGDIM];
    int warp = threadIdx.x >> 5, lane = threadIdx.x & 31;
    int b = blockIdx.x * 8 + warp;
    const float* gp = g_part + (size_t)b * 4 * SIGDIM;
    for (int j = lane; j < SIGDIM; j += 32)
        sh[warp][j] = (gp[j] + gp[SIGDIM + j] + gp[2 * SIGDIM + j] + gp[3 * SIGDIM + j])
                      * (1.0f / (float)KPATHS);
    __syncwarp();

    float logit = -3.402823466e38f;
    if (lane < NCLS) {
        float acc = bf[lane];
        const float* wr = Wf + lane * SIGDIM;
        for (int j = 0; j < SIGDIM; j++) acc = fmaf(sh[warp][j], wr[j], acc);
        logit = acc;
    }
    float mx = logit;
    #pragma unroll
    for (int off = 16; off; off >>= 1)
        mx = fmaxf(mx, __shfl_xor_sync(0xffffffffu, mx, off));
    float e = (lane < NCLS) ? expf(logit - mx) : 0.f;
    float ssum = e;
    #pragma unroll
    for (int off = 16; off; off >>= 1)
        ssum += __shfl_xor_sync(0xffffffffu, ssum, off);
    if (lane < NCLS)
        out[b * NCLS + lane] = logit - mx - logf(ssum);
}

// =====================================================================
extern "C" void kernel_launch(void* const* d_in, const int* in_sizes, int n_in,
                              void* d_out, int out_size)
{
    const float* x      = (const float*)d_in[0];
    const float* W_mean = (const float*)d_in[1];
    const float* b_mean = (const float*)d_in[2];
    const float* W_cov  = (const float*)d_in[3];
    const float* b_cov  = (const float*)d_in[4];
    const float* W_fin  = (const float*)d_in[5];
    const float* b_fin  = (const float*)d_in[6];
    const float* eps    = (const float*)d_in[7];
    const int*   x_idx  = (const int*)  d_in[8];
    const int*   y_idx  = (const int*)  d_in[9];
    float* out = (float*)d_out;

    // 1) fused linears: cov (24 col-blocks) + mean (1 col-block)
    gemm_kernel<<<dim3(25, BATCH / 32), 256>>>(x, W_cov, b_cov, W_mean, b_mean);
    // 2) banded batched matmul -> newV [256,93,64]
    newv_kernel<<<BATCH, 256>>>(eps, x_idx, y_idx);
    // 3) signatures + normalization + partial K-sums (2 kgroups/block)
    sig_kernel<<<BATCH * 2, 512>>>(x);
    // 4) K-mean + final linear + log_softmax
    final_kernel<<<BATCH / 8, 256>>>(W_fin, b_fin, out);
}

// round 7
// speedup vs baseline: 1.2168x; 1.0595x over previous
#include <cuda_runtime.h>

// Problem constants
#define BATCH   256
#define INDIM   159     // L1*(DIM+1) + L2
#define MDIM    93      // L2*DIM
#define MATEL   2976
#define KPATHS  64
#define NCLS    10
#define SIGDIM  340     // 4+16+64+256
#define KD      159
#define KC      40      // gemm k-chunk

// ---------------- scratch (no allocations allowed) ----------------
__device__ __align__(16) float g_mean[BATCH * MDIM];
__device__ __align__(16) float g_cov [BATCH * MATEL];
__device__ __align__(16) float g_newV[BATCH * MDIM * KPATHS];     // [b][r][k]
__device__ __align__(16) float g_part[BATCH * 4 * SIGDIM];        // per (b,kgroup) partials

// =====================================================================
// Kernel 1 (fused): mean = x@W_mean^T + b_mean AND cov = x@W_cov^T + b_cov
// Block tile: 64 batch x 128 n; 8x4 register tile per thread.
// blockIdx.x 0..23 -> cov col-blocks; blockIdx.x == 24 -> mean (N=93).
// =====================================================================
__global__ __launch_bounds__(256) void gemm_kernel(
    const float* __restrict__ X,
    const float* __restrict__ Wc, const float* __restrict__ bc,
    const float* __restrict__ Wm, const float* __restrict__ bm)
{
    __shared__ float Ash[64][KC + 1];   // 10.5 KB
    __shared__ float Wsh[KC][132];      // 20.6 KB (pad; 528B row = 16B aligned)

    bool is_mean = (blockIdx.x == 24);
    const float* W    = is_mean ? Wm : Wc;
    const float* bias = is_mean ? bm : bc;
    float*       out  = is_mean ? g_mean : g_cov;
    int N  = is_mean ? MDIM : MATEL;
    int n0 = is_mean ? 0 : blockIdx.x * 128;
    int b0 = blockIdx.y * 64;
    int tid = threadIdx.x;

    float acc[8][4] = {};
    int tn = tid & 31;          // 4 consecutive n
    int tb = tid >> 5;          // 8 consecutive batch rows

    for (int k0 = 0; k0 < KD; k0 += KC) {
        __syncthreads();
        for (int idx = tid; idx < 64 * KC; idx += 256) {
            int r = idx / KC, k = idx % KC;
            int gk = k0 + k;
            Ash[r][k] = (gk < KD) ? X[(b0 + r) * KD + gk] : 0.f;
        }
        for (int idx = tid; idx < KC * 128; idx += 256) {
            int n = idx / KC, k = idx % KC;
            int gk = k0 + k, gn = n0 + n;
            Wsh[k][n] = (gk < KD && gn < N) ? W[(size_t)gn * KD + gk] : 0.f;
        }
        __syncthreads();
        #pragma unroll 8
        for (int k = 0; k < KC; k++) {
            float4 w = *(const float4*)&Wsh[k][tn * 4];
            #pragma unroll
            for (int j = 0; j < 8; j++) {
                float a = Ash[tb * 8 + j][k];
                acc[j][0] = fmaf(a, w.x, acc[j][0]);
                acc[j][1] = fmaf(a, w.y, acc[j][1]);
                acc[j][2] = fmaf(a, w.z, acc[j][2]);
                acc[j][3] = fmaf(a, w.w, acc[j][3]);
            }
        }
    }
    #pragma unroll
    for (int j = 0; j < 8; j++)
        #pragma unroll
        for (int i = 0; i < 4; i++) {
            int n = n0 + tn * 4 + i;
            if (n < N)
                out[(size_t)(b0 + tb * 8 + j) * N + n] = acc[j][i] + bias[n];
        }
}

// =====================================================================
// Kernel 2: scatter sqrtCov -> banded M (93x93), newV = M@eps + mean.
// 3-row register blocking; balanced band pairing (tg with 30-tg).
// =====================================================================
__global__ __launch_bounds__(256) void newv_kernel(
    const float* __restrict__ eps, const int* __restrict__ xI,
    const int* __restrict__ yI)
{
    __shared__ float Msh[MDIM * MDIM];     // 34.6 KB
    int b   = blockIdx.x;
    int tid = threadIdx.x;

    for (int i = tid; i < MDIM * MDIM; i += 256) Msh[i] = 0.f;
    __syncthreads();
    const float* covB = g_cov + (size_t)b * MATEL;
    for (int e = tid; e < MATEL; e += 256)
        Msh[xI[e] * MDIM + yI[e]] = covB[e];
    __syncthreads();

    int k4 = tid & 15;     // float4 of k
    int tg = tid >> 4;     // band-group 0..15
    const float* epsB = eps    + (size_t)b * MDIM * KPATHS + k4 * 4;
    float*       outB = g_newV + (size_t)b * MDIM * KPATHS + k4 * 4;

    #pragma unroll
    for (int pass = 0; pass < 2; pass++) {
        if (pass == 1 && tg == 15) break;
        int g    = pass ? 30 - tg : tg;
        int r0   = 3 * g;
        int cmax = 3 * g + 3;
        float a0x=0,a0y=0,a0z=0,a0w=0, a1x=0,a1y=0,a1z=0,a1w=0, a2x=0,a2y=0,a2z=0,a2w=0;
        const float* M0 = &Msh[r0 * MDIM];
        for (int c = 0; c < cmax; c++) {
            float4 ev = *(const float4*)(epsB + (size_t)c * KPATHS);
            float m0 = M0[c], m1 = M0[MDIM + c], m2 = M0[2 * MDIM + c];
            a0x = fmaf(m0, ev.x, a0x); a0y = fmaf(m0, ev.y, a0y);
            a0z = fmaf(m0, ev.z, a0z); a0w = fmaf(m0, ev.w, a0w);
            a1x = fmaf(m1, ev.x, a1x); a1y = fmaf(m1, ev.y, a1y);
            a1z = fmaf(m1, ev.z, a1z); a1w = fmaf(m1, ev.w, a1w);
            a2x = fmaf(m2, ev.x, a2x); a2y = fmaf(m2, ev.y, a2y);
            a2z = fmaf(m2, ev.z, a2z); a2w = fmaf(m2, ev.w, a2w);
        }
        float mn0 = g_mean[b * MDIM + r0];
        float mn1 = g_mean[b * MDIM + r0 + 1];
        float mn2 = g_mean[b * MDIM + r0 + 2];
        *(float4*)(outB + (size_t)(r0    ) * KPATHS) = make_float4(a0x+mn0, a0y+mn0, a0z+mn0, a0w+mn0);
        *(float4*)(outB + (size_t)(r0 + 1) * KPATHS) = make_float4(a1x+mn1, a1y+mn1, a1z+mn1, a1w+mn1);
        *(float4*)(outB + (size_t)(r0 + 2) * KPATHS) = make_float4(a2x+mn2, a2y+mn2, a2z+mn2, a2w+mn2);
    }
}

// =====================================================================
// Kernel 3: signature (level 4, D=4) + normalization + partial K-mean.
// 16 lanes per path (prefix i1,i2); S2/S3/S4 register-resident.
// Lambda solve: Newton on t=lam^2 from a provable upper bound on the
// root (min_k ((psi-1)/n_k)^{1/k}); monotone + quadratic => 12 iters.
// =====================================================================
#define SIG_STEP(c0_, c1_, c2_, c3_) do {                                         \
    float dx0 = (c0_) - p0, dx1 = (c1_) - p1, dx2 = (c2_) - p2, dx3 = (c3_) - p3; \
    p0 = (c0_); p1 = (c1_); p2 = (c2_); p3 = (c3_);                               \
    float du = (i1 == 0) ? dx0 : ((i1 == 1) ? dx1 : ((i1 == 2) ? dx2 : dx3));     \
    float dv = (i2 == 0) ? dx0 : ((i2 == 1) ? dx1 : ((i2 == 2) ? dx2 : dx3));     \
    float cc1 = fmaf(0.25f, du, s1u);                                             \
    float cc2 = fmaf((1.0f/3.0f) * dv, cc1, s2);                                  \
    float hh;                                                                     \
    hh = fmaf(0.5f*dx0, cc2, s3[0]);                                              \
    s4[0] = fmaf(dx0,hh,s4[0]);  s4[1] = fmaf(dx1,hh,s4[1]);                      \
    s4[2] = fmaf(dx2,hh,s4[2]);  s4[3] = fmaf(dx3,hh,s4[3]);                      \
    hh = fmaf(0.5f*dx1, cc2, s3[1]);                                              \
    s4[4] = fmaf(dx0,hh,s4[4]);  s4[5] = fmaf(dx1,hh,s4[5]);                      \
    s4[6] = fmaf(dx2,hh,s4[6]);  s4[7] = fmaf(dx3,hh,s4[7]);                      \
    hh = fmaf(0.5f*dx2, cc2, s3[2]);                                              \
    s4[8] = fmaf(dx0,hh,s4[8]);  s4[9] = fmaf(dx1,hh,s4[9]);                      \
    s4[10]= fmaf(dx2,hh,s4[10]); s4[11]= fmaf(dx3,hh,s4[11]);                     \
    hh = fmaf(0.5f*dx3, cc2, s3[3]);                                              \
    s4[12]= fmaf(dx0,hh,s4[12]); s4[13]= fmaf(dx1,hh,s4[13]);                     \
    s4[14]= fmaf(dx2,hh,s4[14]); s4[15]= fmaf(dx3,hh,s4[15]);                     \
    float c1b = fmaf((1.0f/3.0f), du, s1u);                                       \
    float m3v = fmaf(0.5f*dv, c1b, s2);                                           \
    s3[0] = fmaf(dx0, m3v, s3[0]); s3[1] = fmaf(dx1, m3v, s3[1]);                 \
    s3[2] = fmaf(dx2, m3v, s3[2]); s3[3] = fmaf(dx3, m3v, s3[3]);                 \
    s2 = fmaf(dv, fmaf(0.5f, du, s1u), s2);                                       \
    s1u += du;                                                                    \
} while (0)

__global__ __launch_bounds__(512, 2) void sig_kernel(const float* __restrict__ x)
{
    __shared__ float4 ksh4[32];             // known points (coords, t)
    __shared__ float4 nsh4[2][31][16];      // new points [kgl][m][p]
    __shared__ float  sacc[2][SIGDIM];

    int b    = blockIdx.x >> 1;
    int half = blockIdx.x & 1;
    int tid  = threadIdx.x;
    const float* xb = x + (size_t)b * INDIM;

    if (tid < 32)
        ksh4[tid] = make_float4(xb[3*tid], xb[3*tid+1], xb[3*tid+2], xb[96 + tid]);

    const float* nvb = g_newV + (size_t)b * MDIM * KPATHS + half * 32;
    for (int i = tid; i < 2 * 31 * 3 * 16; i += 512) {
        int p = i & 15;
        int t1 = i >> 4;
        int j  = t1 % 3;
        int t2 = t1 / 3;
        int m  = t2 % 31;
        int kgl = t2 / 31;
        ((float*)&nsh4[kgl][m][p])[j] = nvb[(size_t)(3*m + j) * KPATHS + kgl * 16 + p];
    }
    for (int i = tid; i < 2 * 31 * 16; i += 512) {
        int p = i & 15;
        int t = i >> 4;
        int m = t % 31;
        int kgl = t / 31;
        ((float*)&nsh4[kgl][m][p])[3] = xb[128 + m];
    }
    for (int i = tid; i < 2 * SIGDIM; i += 512) sacc[0][i] = 0.f;
    __syncthreads();

    int path = tid >> 4;        // 0..31
    int kgl  = path >> 4;
    int p16  = path & 15;
    int pre  = tid & 15;
    int i1 = pre >> 2, i2 = pre & 3;
    const float4* nrow = &nsh4[kgl][0][p16];

    float4 P0 = ksh4[0];
    float p0 = P0.x, p1 = P0.y, p2 = P0.z, p3 = P0.w;
    float s1u = 0.f, s2 = 0.f;
    float s3[4] = {0.f, 0.f, 0.f, 0.f};
    float s4[16] = {0.f,0.f,0.f,0.f,0.f,0.f,0.f,0.f,0.f,0.f,0.f,0.f,0.f,0.f,0.f,0.f};

    float4 cn = nrow[0];
    float4 ck = ksh4[1];
    for (int m = 0; m < 31; m++) {
        int mn = (m < 30) ? m + 1 : 30;
        float4 cnN = nrow[mn * 16];
        float4 ckN = ksh4[mn + 1];
        SIG_STEP(cn.x, cn.y, cn.z, cn.w);    // midpoint m (id 32+m)
        SIG_STEP(ck.x, ck.y, ck.z, ck.w);    // known point m+1
        cn = cnN; ck = ckN;
    }

    float s1x = p0 - P0.x, s1y = p1 - P0.y, s1z = p2 - P0.z, s1t = p3 - P0.w;

    // ---- norms (reduce over 16 prefix lanes) ----
    float n1 = s1x*s1x + s1y*s1y + s1z*s1z + s1t*s1t;   // replicated
    float n2 = s2 * s2;
    float n3 = s3[0]*s3[0] + s3[1]*s3[1] + s3[2]*s3[2] + s3[3]*s3[3];
    float n4 = 0.f;
    #pragma unroll
    for (int j = 0; j < 16; j++) n4 = fmaf(s4[j], s4[j], n4);
    #pragma unroll
    for (int off = 8; off >= 1; off >>= 1) {
        n2 += __shfl_xor_sync(0xffffffffu, n2, off);
        n3 += __shfl_xor_sync(0xffffffffu, n3, off);
        n4 += __shfl_xor_sync(0xffffffffu, n4, off);
    }

    float norm2 = 1.0f + (((n1 + n2) + n3) + n4);
    float xc  = fmaxf(norm2, 4.0f);
    float psi = (norm2 <= 4.0f) ? norm2 : (4.0f + 16.0f * (0.25f - 1.0f / xc));

    // Solve 1 + n1 t + n2 t^2 + n3 t^3 + n4 t^4 = psi for t = lam^2.
    // f(t) = sum - (psi-1): convex, increasing on t>0, f(1) >= 0.
    // Root upper bounds: t* <= ((psi-1)/n_k)^{1/k} for each k (terms are
    // nonnegative). Start at min(1, bounds); Newton from an upper bound on a
    // convex function descends monotonically, never undershoots, quadratic.
    float q = psi - 1.0f;                       // >= 0
    float t = 1.0f;
    t = fminf(t, q / n1);                       // n_k==0 -> inf/NaN -> fminf keeps t
    t = fminf(t, sqrtf(q / n2));
    t = fminf(t, exp2f((1.0f/3.0f) * log2f(q / n3)));
    t = fminf(t, sqrtf(sqrtf(q / n4)));
    float cN = -q;
    #pragma unroll
    for (int it = 0; it < 12; it++) {
        float f  = fmaf(fmaf(fmaf(fmaf(n4, t, n3), t, n2), t, n1), t, cN);
        float fp = fmaf(fmaf(fmaf(4.0f*n4, t, 3.0f*n3), t, 2.0f*n2), t, n1);
        fp = fmaxf(fp, 1e-30f);
        t  = fmaxf(t - f / fp, 0.0f);
    }
    float lam2 = t;
    float lam  = sqrtf(t);
    float lam3 = lam2 * lam, lam4 = lam2 * lam2;

    float* sa = sacc[kgl];
    if (pre == 0) {
        atomicAdd(&sa[0], lam * s1x);
        atomicAdd(&sa[1], lam * s1y);
        atomicAdd(&sa[2], lam * s1z);
        atomicAdd(&sa[3], lam * s1t);
    }
    atomicAdd(&sa[4 + pre], lam2 * s2);
    #pragma unroll
    for (int j = 0; j < 4; j++)
        atomicAdd(&sa[20 + pre * 4 + j], lam3 * s3[j]);
    #pragma unroll
    for (int j = 0; j < 16; j++)
        atomicAdd(&sa[84 + pre * 16 + j], lam4 * s4[j]);
    __syncthreads();

    for (int i = tid; i < 2 * SIGDIM; i += 512) {
        int kg2 = i / SIGDIM, r = i % SIGDIM;
        g_part[(size_t)(b * 4 + half * 2 + kg2) * SIGDIM + r] = sacc[kg2][r];
    }
}

// =====================================================================
// Kernel 4: K-mean, final linear (10x340), log_softmax. Warp per batch.
// Lane-parallel dot products + butterfly reductions.
// =====================================================================
__global__ __launch_bounds__(256) void final_kernel(
    const float* __restrict__ Wf, const float* __restrict__ bf,
    float* __restrict__ out)
{
    __shared__ float sh[8][SIGDIM];
    int warp = threadIdx.x >> 5, lane = threadIdx.x & 31;
    int b = blockIdx.x * 8 + warp;
    const float* gp = g_part + (size_t)b * 4 * SIGDIM;
    for (int j = lane; j < SIGDIM; j += 32)
        sh[warp][j] = (gp[j] + gp[SIGDIM + j] + gp[2 * SIGDIM + j] + gp[3 * SIGDIM + j])
                      * (1.0f / (float)KPATHS);
    __syncwarp();

    float acc[NCLS];
    #pragma unroll
    for (int c = 0; c < NCLS; c++) acc[c] = 0.f;
    #pragma unroll
    for (int i = 0; i < 11; i++) {
        int j = lane + i * 32;
        if (j < SIGDIM) {
            float v = sh[warp][j];
            #pragma unroll
            for (int c = 0; c < NCLS; c++)
                acc[c] = fmaf(v, __ldg(&Wf[c * SIGDIM + j]), acc[c]);
        }
    }
    #pragma unroll
    for (int c = 0; c < NCLS; c++)
        #pragma unroll
        for (int off = 16; off; off >>= 1)
            acc[c] += __shfl_xor_sync(0xffffffffu, acc[c], off);

    float logit = -3.402823466e38f;
    #pragma unroll
    for (int c = 0; c < NCLS; c++)
        if (lane == c) logit = acc[c] + bf[c];

    float mx = logit;
    #pragma unroll
    for (int off = 16; off; off >>= 1)
        mx = fmaxf(mx, __shfl_xor_sync(0xffffffffu, mx, off));
    float e = (lane < NCLS) ? expf(logit - mx) : 0.f;
    float ssum = e;
    #pragma unroll
    for (int off = 16; off; off >>= 1)
        ssum += __shfl_xor_sync(0xffffffffu, ssum, off);
    if (lane < NCLS)
        out[b * NCLS + lane] = logit - mx - logf(ssum);
}

// =====================================================================
extern "C" void kernel_launch(void* const* d_in, const int* in_sizes, int n_in,
                              void* d_out, int out_size)
{
    const float* x      = (const float*)d_in[0];
    const float* W_mean = (const float*)d_in[1];
    const float* b_mean = (const float*)d_in[2];
    const float* W_cov  = (const float*)d_in[3];
    const float* b_cov  = (const float*)d_in[4];
    const float* W_fin  = (const float*)d_in[5];
    const float* b_fin  = (const float*)d_in[6];
    const float* eps    = (const float*)d_in[7];
    const int*   x_idx  = (const int*)  d_in[8];
    const int*   y_idx  = (const int*)  d_in[9];
    float* out = (float*)d_out;

    // 1) fused linears: cov (24 col-blocks) + mean (1 col-block)
    gemm_kernel<<<dim3(25, BATCH / 64), 256>>>(x, W_cov, b_cov, W_mean, b_mean);
    // 2) banded batched matmul -> newV [256,93,64]
    newv_kernel<<<BATCH, 256>>>(eps, x_idx, y_idx);
    // 3) signatures + normalization + partial K-sums (2 kgroups/block)
    sig_kernel<<<BATCH * 2, 512>>>(x);
    // 4) K-mean + final linear + log_softmax
    final_kernel<<<BATCH / 8, 256>>>(W_fin, b_fin, out);
}

// round 8
// speedup vs baseline: 1.2413x; 1.0201x over previous
#include <cuda_runtime.h>

// Problem constants
#define BATCH   256
#define INDIM   159     // L1*(DIM+1) + L2
#define MDIM    93      // L2*DIM
#define MATEL   2976
#define KPATHS  64
#define NCLS    10
#define SIGDIM  340     // 4+16+64+256
#define KD      159
#define KC      40      // gemm k-chunk

// ---------------- scratch (no allocations allowed) ----------------
__device__ __align__(16) float g_mean[BATCH * MDIM];
__device__ __align__(16) float g_cov [BATCH * MATEL];
__device__ __align__(16) float g_newV[BATCH * MDIM * KPATHS];     // [b][r][k]
__device__ __align__(16) float g_logits[BATCH * NCLS];            // atomic accumulators

// =====================================================================
// Kernel 1 (fused): mean = x@W_mean^T + b_mean AND cov = x@W_cov^T + b_cov
// Block tile: 64 batch x 128 n; 8x4 register tile per thread.
// blockIdx.x 0..23 -> cov col-blocks; blockIdx.x == 24 -> mean (N=93).
// The is_mean blocks also zero g_logits (stream-ordered before sig_kernel).
// =====================================================================
__global__ __launch_bounds__(256) void gemm_kernel(
    const float* __restrict__ X,
    const float* __restrict__ Wc, const float* __restrict__ bc,
    const float* __restrict__ Wm, const float* __restrict__ bm)
{
    __shared__ float Ash[64][KC + 1];   // 10.5 KB
    __shared__ float Wsh[KC][132];      // 20.6 KB (pad; 528B row = 16B aligned)

    bool is_mean = (blockIdx.x == 24);
    const float* W    = is_mean ? Wm : Wc;
    const float* bias = is_mean ? bm : bc;
    float*       out  = is_mean ? g_mean : g_cov;
    int N  = is_mean ? MDIM : MATEL;
    int n0 = is_mean ? 0 : blockIdx.x * 128;
    int b0 = blockIdx.y * 64;
    int tid = threadIdx.x;

    if (is_mean)    // zero logit accumulators (all 4 y-blocks write 0: benign)
        for (int i = tid; i < BATCH * NCLS; i += 256) g_logits[i] = 0.f;

    float acc[8][4] = {};
    int tn = tid & 31;          // 4 consecutive n
    int tb = tid >> 5;          // 8 consecutive batch rows

    for (int k0 = 0; k0 < KD; k0 += KC) {
        __syncthreads();
        for (int idx = tid; idx < 64 * KC; idx += 256) {
            int r = idx / KC, k = idx % KC;
            int gk = k0 + k;
            Ash[r][k] = (gk < KD) ? X[(b0 + r) * KD + gk] : 0.f;
        }
        for (int idx = tid; idx < KC * 128; idx += 256) {
            int n = idx / KC, k = idx % KC;
            int gk = k0 + k, gn = n0 + n;
            Wsh[k][n] = (gk < KD && gn < N) ? W[(size_t)gn * KD + gk] : 0.f;
        }
        __syncthreads();
        #pragma unroll 8
        for (int k = 0; k < KC; k++) {
            float4 w = *(const float4*)&Wsh[k][tn * 4];
            #pragma unroll
            for (int j = 0; j < 8; j++) {
                float a = Ash[tb * 8 + j][k];
                acc[j][0] = fmaf(a, w.x, acc[j][0]);
                acc[j][1] = fmaf(a, w.y, acc[j][1]);
                acc[j][2] = fmaf(a, w.z, acc[j][2]);
                acc[j][3] = fmaf(a, w.w, acc[j][3]);
            }
        }
    }
    #pragma unroll
    for (int j = 0; j < 8; j++)
        #pragma unroll
        for (int i = 0; i < 4; i++) {
            int n = n0 + tn * 4 + i;
            if (n < N)
                out[(size_t)(b0 + tb * 8 + j) * N + n] = acc[j][i] + bias[n];
        }
}

// =====================================================================
// Kernel 2: scatter sqrtCov -> banded M (93x93), newV = M@eps + mean.
// 3-row register blocking; balanced band pairing (tg with 30-tg).
// =====================================================================
__global__ __launch_bounds__(256) void newv_kernel(
    const float* __restrict__ eps, const int* __restrict__ xI,
    const int* __restrict__ yI)
{
    __shared__ float Msh[MDIM * MDIM];     // 34.6 KB
    int b   = blockIdx.x;
    int tid = threadIdx.x;

    for (int i = tid; i < MDIM * MDIM; i += 256) Msh[i] = 0.f;
    __syncthreads();
    const float* covB = g_cov + (size_t)b * MATEL;
    for (int e = tid; e < MATEL; e += 256)
        Msh[xI[e] * MDIM + yI[e]] = covB[e];
    __syncthreads();

    int k4 = tid & 15;     // float4 of k
    int tg = tid >> 4;     // band-group 0..15
    const float* epsB = eps    + (size_t)b * MDIM * KPATHS + k4 * 4;
    float*       outB = g_newV + (size_t)b * MDIM * KPATHS + k4 * 4;

    #pragma unroll
    for (int pass = 0; pass < 2; pass++) {
        if (pass == 1 && tg == 15) break;
        int g    = pass ? 30 - tg : tg;
        int r0   = 3 * g;
        int cmax = 3 * g + 3;
        float a0x=0,a0y=0,a0z=0,a0w=0, a1x=0,a1y=0,a1z=0,a1w=0, a2x=0,a2y=0,a2z=0,a2w=0;
        const float* M0 = &Msh[r0 * MDIM];
        for (int c = 0; c < cmax; c++) {
            float4 ev = *(const float4*)(epsB + (size_t)c * KPATHS);
            float m0 = M0[c], m1 = M0[MDIM + c], m2 = M0[2 * MDIM + c];
            a0x = fmaf(m0, ev.x, a0x); a0y = fmaf(m0, ev.y, a0y);
            a0z = fmaf(m0, ev.z, a0z); a0w = fmaf(m0, ev.w, a0w);
            a1x = fmaf(m1, ev.x, a1x); a1y = fmaf(m1, ev.y, a1y);
            a1z = fmaf(m1, ev.z, a1z); a1w = fmaf(m1, ev.w, a1w);
            a2x = fmaf(m2, ev.x, a2x); a2y = fmaf(m2, ev.y, a2y);
            a2z = fmaf(m2, ev.z, a2z); a2w = fmaf(m2, ev.w, a2w);
        }
        float mn0 = g_mean[b * MDIM + r0];
        float mn1 = g_mean[b * MDIM + r0 + 1];
        float mn2 = g_mean[b * MDIM + r0 + 2];
        *(float4*)(outB + (size_t)(r0    ) * KPATHS) = make_float4(a0x+mn0, a0y+mn0, a0z+mn0, a0w+mn0);
        *(float4*)(outB + (size_t)(r0 + 1) * KPATHS) = make_float4(a1x+mn1, a1y+mn1, a1z+mn1, a1w+mn1);
        *(float4*)(outB + (size_t)(r0 + 2) * KPATHS) = make_float4(a2x+mn2, a2y+mn2, a2z+mn2, a2w+mn2);
    }
}

// =====================================================================
// Kernel 3: signature (level 4, D=4) + normalization + in-block final
// linear contraction. 16 lanes per path (prefix i1,i2); S2/S3/S4
// register-resident. After sacc is built, 20 warp-level dot products
// against W_fin produce this block's logit contributions -> global
// atomicAdd (g_logits). No bulk intermediate leaves the block.
// =====================================================================
#define SIG_STEP(c0_, c1_, c2_, c3_) do {                                         \
    float dx0 = (c0_) - p0, dx1 = (c1_) - p1, dx2 = (c2_) - p2, dx3 = (c3_) - p3; \
    p0 = (c0_); p1 = (c1_); p2 = (c2_); p3 = (c3_);                               \
    float du = (i1 == 0) ? dx0 : ((i1 == 1) ? dx1 : ((i1 == 2) ? dx2 : dx3));     \
    float dv = (i2 == 0) ? dx0 : ((i2 == 1) ? dx1 : ((i2 == 2) ? dx2 : dx3));     \
    float cc1 = fmaf(0.25f, du, s1u);                                             \
    float cc2 = fmaf((1.0f/3.0f) * dv, cc1, s2);                                  \
    float hh;                                                                     \
    hh = fmaf(0.5f*dx0, cc2, s3[0]);                                              \
    s4[0] = fmaf(dx0,hh,s4[0]);  s4[1] = fmaf(dx1,hh,s4[1]);                      \
    s4[2] = fmaf(dx2,hh,s4[2]);  s4[3] = fmaf(dx3,hh,s4[3]);                      \
    hh = fmaf(0.5f*dx1, cc2, s3[1]);                                              \
    s4[4] = fmaf(dx0,hh,s4[4]);  s4[5] = fmaf(dx1,hh,s4[5]);                      \
    s4[6] = fmaf(dx2,hh,s4[6]);  s4[7] = fmaf(dx3,hh,s4[7]);                      \
    hh = fmaf(0.5f*dx2, cc2, s3[2]);                                              \
    s4[8] = fmaf(dx0,hh,s4[8]);  s4[9] = fmaf(dx1,hh,s4[9]);                      \
    s4[10]= fmaf(dx2,hh,s4[10]); s4[11]= fmaf(dx3,hh,s4[11]);                     \
    hh = fmaf(0.5f*dx3, cc2, s3[3]);                                              \
    s4[12]= fmaf(dx0,hh,s4[12]); s4[13]= fmaf(dx1,hh,s4[13]);                     \
    s4[14]= fmaf(dx2,hh,s4[14]); s4[15]= fmaf(dx3,hh,s4[15]);                     \
    float c1b = fmaf((1.0f/3.0f), du, s1u);                                       \
    float m3v = fmaf(0.5f*dv, c1b, s2);                                           \
    s3[0] = fmaf(dx0, m3v, s3[0]); s3[1] = fmaf(dx1, m3v, s3[1]);                 \
    s3[2] = fmaf(dx2, m3v, s3[2]); s3[3] = fmaf(dx3, m3v, s3[3]);                 \
    s2 = fmaf(dv, fmaf(0.5f, du, s1u), s2);                                       \
    s1u += du;                                                                    \
} while (0)

__global__ __launch_bounds__(512, 2) void sig_kernel(
    const float* __restrict__ x, const float* __restrict__ Wf)
{
    __shared__ float4 ksh4[32];             // known points (coords, t)
    __shared__ float4 nsh4[2][31][16];      // new points [kgl][m][p]
    __shared__ float  sacc[2][SIGDIM];

    int b    = blockIdx.x >> 1;
    int half = blockIdx.x & 1;
    int tid  = threadIdx.x;
    const float* xb = x + (size_t)b * INDIM;

    if (tid < 32)
        ksh4[tid] = make_float4(xb[3*tid], xb[3*tid+1], xb[3*tid+2], xb[96 + tid]);

    const float* nvb = g_newV + (size_t)b * MDIM * KPATHS + half * 32;
    for (int i = tid; i < 2 * 31 * 3 * 16; i += 512) {
        int p = i & 15;
        int t1 = i >> 4;
        int j  = t1 % 3;
        int t2 = t1 / 3;
        int m  = t2 % 31;
        int kgl = t2 / 31;
        ((float*)&nsh4[kgl][m][p])[j] = nvb[(size_t)(3*m + j) * KPATHS + kgl * 16 + p];
    }
    for (int i = tid; i < 2 * 31 * 16; i += 512) {
        int p = i & 15;
        int t = i >> 4;
        int m = t % 31;
        int kgl = t / 31;
        ((float*)&nsh4[kgl][m][p])[3] = xb[128 + m];
    }
    for (int i = tid; i < 2 * SIGDIM; i += 512) sacc[0][i] = 0.f;
    __syncthreads();

    int path = tid >> 4;        // 0..31
    int kgl  = path >> 4;
    int p16  = path & 15;
    int pre  = tid & 15;
    int i1 = pre >> 2, i2 = pre & 3;
    const float4* nrow = &nsh4[kgl][0][p16];

    float4 P0 = ksh4[0];
    float p0 = P0.x, p1 = P0.y, p2 = P0.z, p3 = P0.w;
    float s1u = 0.f, s2 = 0.f;
    float s3[4] = {0.f, 0.f, 0.f, 0.f};
    float s4[16] = {0.f,0.f,0.f,0.f,0.f,0.f,0.f,0.f,0.f,0.f,0.f,0.f,0.f,0.f,0.f,0.f};

    float4 cn = nrow[0];
    float4 ck = ksh4[1];
    for (int m = 0; m < 31; m++) {
        int mn = (m < 30) ? m + 1 : 30;
        float4 cnN = nrow[mn * 16];
        float4 ckN = ksh4[mn + 1];
        SIG_STEP(cn.x, cn.y, cn.z, cn.w);    // midpoint m (id 32+m)
        SIG_STEP(ck.x, ck.y, ck.z, ck.w);    // known point m+1
        cn = cnN; ck = ckN;
    }

    float s1x = p0 - P0.x, s1y = p1 - P0.y, s1z = p2 - P0.z, s1t = p3 - P0.w;

    // ---- norms (reduce over 16 prefix lanes) ----
    float n1 = s1x*s1x + s1y*s1y + s1z*s1z + s1t*s1t;   // replicated
    float n2 = s2 * s2;
    float n3 = s3[0]*s3[0] + s3[1]*s3[1] + s3[2]*s3[2] + s3[3]*s3[3];
    float n4 = 0.f;
    #pragma unroll
    for (int j = 0; j < 16; j++) n4 = fmaf(s4[j], s4[j], n4);
    #pragma unroll
    for (int off = 8; off >= 1; off >>= 1) {
        n2 += __shfl_xor_sync(0xffffffffu, n2, off);
        n3 += __shfl_xor_sync(0xffffffffu, n3, off);
        n4 += __shfl_xor_sync(0xffffffffu, n4, off);
    }

    float norm2 = 1.0f + (((n1 + n2) + n3) + n4);
    float xc  = fmaxf(norm2, 4.0f);
    float psi = (norm2 <= 4.0f) ? norm2 : (4.0f + 16.0f * (0.25f - 1.0f / xc));

    // Newton on t = lam^2 from a provable root upper bound; convex,
    // increasing, monotone descent, quadratic convergence.
    float q = psi - 1.0f;                       // >= 0
    float t = 1.0f;
    t = fminf(t, q / n1);                       // n_k==0 -> inf/NaN -> fminf keeps t
    t = fminf(t, sqrtf(q / n2));
    t = fminf(t, exp2f((1.0f/3.0f) * log2f(q / n3)));
    t = fminf(t, sqrtf(sqrtf(q / n4)));
    float cN = -q;
    #pragma unroll
    for (int it = 0; it < 12; it++) {
        float f  = fmaf(fmaf(fmaf(fmaf(n4, t, n3), t, n2), t, n1), t, cN);
        float fp = fmaf(fmaf(fmaf(4.0f*n4, t, 3.0f*n3), t, 2.0f*n2), t, n1);
        fp = fmaxf(fp, 1e-30f);
        t  = fmaxf(t - f / fp, 0.0f);
    }
    float lam2 = t;
    float lam  = sqrtf(t);
    float lam3 = lam2 * lam, lam4 = lam2 * lam2;

    float* sa = sacc[kgl];
    if (pre == 0) {
        atomicAdd(&sa[0], lam * s1x);
        atomicAdd(&sa[1], lam * s1y);
        atomicAdd(&sa[2], lam * s1z);
        atomicAdd(&sa[3], lam * s1t);
    }
    atomicAdd(&sa[4 + pre], lam2 * s2);
    #pragma unroll
    for (int j = 0; j < 4; j++)
        atomicAdd(&sa[20 + pre * 4 + j], lam3 * s3[j]);
    #pragma unroll
    for (int j = 0; j < 16; j++)
        atomicAdd(&sa[84 + pre * 16 + j], lam4 * s4[j]);
    __syncthreads();

    // ---- in-block final-linear contraction: 20 (class, kgroup) dots ----
    int warp = tid >> 5, lane = tid & 31;
    for (int pair = warp; pair < 2 * NCLS; pair += 16) {
        int c = pair >> 1, kg2 = pair & 1;
        float sum = 0.f;
        #pragma unroll
        for (int i = 0; i < 11; i++) {
            int j = lane + i * 32;
            if (j < SIGDIM)
                sum = fmaf(sacc[kg2][j], __ldg(&Wf[c * SIGDIM + j]), sum);
        }
        #pragma unroll
        for (int off = 16; off; off >>= 1)
            sum += __shfl_xor_sync(0xffffffffu, sum, off);
        if (lane == 0)
            atomicAdd(&g_logits[b * NCLS + c], sum);
    }
}

// =====================================================================
// Kernel 4: scale + bias + log_softmax on the 256x10 logits. Tiny.
// =====================================================================
__global__ __launch_bounds__(256) void final_kernel(
    const float* __restrict__ bf, float* __restrict__ out)
{
    int warp = threadIdx.x >> 5, lane = threadIdx.x & 31;
    int b = blockIdx.x * 8 + warp;

    float logit = -3.402823466e38f;
    if (lane < NCLS)
        logit = g_logits[b * NCLS + lane] * (1.0f / (float)KPATHS) + bf[lane];

    float mx = logit;
    #pragma unroll
    for (int off = 16; off; off >>= 1)
        mx = fmaxf(mx, __shfl_xor_sync(0xffffffffu, mx, off));
    float e = (lane < NCLS) ? expf(logit - mx) : 0.f;
    float ssum = e;
    #pragma unroll
    for (int off = 16; off; off >>= 1)
        ssum += __shfl_xor_sync(0xffffffffu, ssum, off);
    if (lane < NCLS)
        out[b * NCLS + lane] = logit - mx - logf(ssum);
}

// =====================================================================
extern "C" void kernel_launch(void* const* d_in, const int* in_sizes, int n_in,
                              void* d_out, int out_size)
{
    const float* x      = (const float*)d_in[0];
    const float* W_mean = (const float*)d_in[1];
    const float* b_mean = (const float*)d_in[2];
    const float* W_cov  = (const float*)d_in[3];
    const float* b_cov  = (const float*)d_in[4];
    const float* W_fin  = (const float*)d_in[5];
    const float* b_fin  = (const float*)d_in[6];
    const float* eps    = (const float*)d_in[7];
    const int*   x_idx  = (const int*)  d_in[8];
    const int*   y_idx  = (const int*)  d_in[9];
    float* out = (float*)d_out;

    // 1) fused linears (also zeroes g_logits in is_mean blocks)
    gemm_kernel<<<dim3(25, BATCH / 64), 256>>>(x, W_cov, b_cov, W_mean, b_mean);
    // 2) banded batched matmul -> newV [256,93,64]
    newv_kernel<<<BATCH, 256>>>(eps, x_idx, y_idx);
    // 3) signatures + normalization + logit contraction (atomic)
    sig_kernel<<<BATCH * 2, 512>>>(x, W_fin);
    // 4) bias + log_softmax
    final_kernel<<<BATCH / 8, 256>>>(b_fin, out);
}